// round 9
// baseline (speedup 1.0000x reference)
#include <cuda_runtime.h>
#include <cuda_bf16.h>
#include <cstdint>
#include <math.h>

// Problem constants
#define BB 8
#define SS 512
#define HH 768
#define NHH 12
#define DHH 64
#define LL 12
#define VV 21128
#define FFF 3072
#define PLEN 128
#define NTOK (BB*SS)
#define NVALID_PER_B (SS-PLEN)
#define NVALID (BB*NVALID_PER_B)
#define QKVW (3*HH)            // 2304

// ---------------- scratch (device globals; no allocations allowed) ----------
__device__ float g_h[NTOK*HH];
__device__ float g_qkv[(size_t)NTOK*QKVW];
__device__ float g_ctx[NTOK*HH];
__device__ float g_tmp[NTOK*HH];
__device__ float g_ffn[NTOK*FFF];
__device__ float g_scores[(size_t)BB*NHH*SS*SS];
__device__ float g_logits[(size_t)NVALID*VV];
__device__ float g_wqkv[(size_t)LL*HH*QKVW];
__device__ float g_bqkv[(size_t)LL*QKVW];
__device__ float g_loss_sum;

// ---------------- helpers ----------------------------------------------------
__device__ __forceinline__ float warpSum(float v){
  #pragma unroll
  for (int o=16;o;o>>=1) v += __shfl_xor_sync(0xffffffffu, v, o);
  return v;
}
__device__ __forceinline__ float warpMax(float v){
  #pragma unroll
  for (int o=16;o;o>>=1) v = fmaxf(v, __shfl_xor_sync(0xffffffffu, v, o));
  return v;
}
template<int NW>
__device__ __forceinline__ float blockSum(float v){
  __shared__ float sh[NW];
  __syncthreads();
  v = warpSum(v);
  if ((threadIdx.x & 31)==0) sh[threadIdx.x>>5] = v;
  __syncthreads();
  float r = 0.f;
  #pragma unroll
  for (int i=0;i<NW;i++) r += sh[i];
  return r;
}
template<int NW>
__device__ __forceinline__ float blockMax(float v){
  __shared__ float sh[NW];
  __syncthreads();
  v = warpMax(v);
  if ((threadIdx.x & 31)==0) sh[threadIdx.x>>5] = v;
  __syncthreads();
  float r = -3.4e38f;
  #pragma unroll
  for (int i=0;i<NW;i++) r = fmaxf(r, sh[i]);
  return r;
}
__device__ __forceinline__ float gelu_exact(float x){
  return 0.5f * x * (1.0f + erff(x * 0.70710678118654752f));
}

__device__ __forceinline__ uint32_t smem_u32(const void* p){
  uint32_t a;
  asm("{ .reg .u64 t; cvta.to.shared.u64 t, %1; cvt.u32.u64 %0, t; }" : "=r"(a) : "l"(p));
  return a;
}

// split a pair of fp32 into packed bf16 hi and packed bf16 lo (x0 -> low half)
__device__ __forceinline__ void split_bf16_pair(float x0, float x1,
                                                uint32_t& hi, uint32_t& lo){
  uint32_t h;
  asm("cvt.rn.bf16x2.f32 %0, %1, %2;" : "=r"(h) : "f"(x1), "f"(x0));
  float h0 = __uint_as_float(h << 16);
  float h1 = __uint_as_float(h & 0xffff0000u);
  float l0 = x0 - h0;
  float l1 = x1 - h1;
  asm("cvt.rn.bf16x2.f32 %0, %1, %2;" : "=r"(lo) : "f"(l1), "f"(l0));
  hi = h;
}

__device__ __forceinline__ void mma_bf16(float* d, const uint32_t* a, const uint32_t* b){
  asm volatile(
    "mma.sync.aligned.m16n8k16.row.col.f32.bf16.bf16.f32 "
    "{%0,%1,%2,%3}, {%4,%5,%6,%7}, {%8,%9}, {%0,%1,%2,%3};\n"
    : "+f"(d[0]), "+f"(d[1]), "+f"(d[2]), "+f"(d[3])
    : "r"(a[0]), "r"(a[1]), "r"(a[2]), "r"(a[3]), "r"(b[0]), "r"(b[1]));
}
__device__ __forceinline__ void ldsm_x4(uint32_t* r, uint32_t addr){
  asm volatile("ldmatrix.sync.aligned.m8n8.x4.shared.b16 {%0,%1,%2,%3}, [%4];"
    : "=r"(r[0]), "=r"(r[1]), "=r"(r[2]), "=r"(r[3]) : "r"(addr));
}
__device__ __forceinline__ void ldsm_x4_t(uint32_t* r, uint32_t addr){
  asm volatile("ldmatrix.sync.aligned.m8n8.x4.trans.shared.b16 {%0,%1,%2,%3}, [%4];"
    : "=r"(r[0]), "=r"(r[1]), "=r"(r[2]), "=r"(r[3]) : "r"(addr));
}

// ---------------- 3xBF16 mma.sync GEMM, BN=64 tiles, 2 CTAs/SM ---------------
// C[M,N] = A[M,K] @ op(B) (+bias)(+GELU). TRANSB: B is [N,K] (NT, C=A@B^T);
// else B is [K,N] (NN). BM=128, BK=16, warp tile 32x32 (8 warps), single
// __syncthreads per chunk, register-prefetch double buffering,
// pre-split bf16 hi/lo smem + ldmatrix fragments.
// maskMode: 0 = none; 1 = prefix-LM scores (skip CTA if n0 >= m0+128);
//           2 = prefix-LM AV (truncate K loop at m0+128).

template<int BN, bool TRANSB, int ACT>
__global__ __launch_bounds__(256,2) void gemm_mma(
    const float* __restrict__ Ag, const float* __restrict__ Bg,
    const float* __restrict__ bias, float* __restrict__ Cg,
    int M, int N, int K, int lda, int ldb, int ldc,
    int batchInner,
    long long sA1, long long sA2, long long sB1, long long sB2,
    long long sC1, long long sC2, int maskMode)
{
  constexpr int BM = 128;
  constexpr int BK = 16;
  constexpr int WARPS_N = BN/32;         // 2
  constexpr int WARPS_M = 8/WARPS_N;     // 4
  constexpr int WM = BM / WARPS_M;       // 32
  constexpr int WN = BN / WARPS_N;       // 32
  constexpr int MF = WM / 16;            // 2
  constexpr int NF = WN / 8;             // 4

  constexpr int AP = 24;                            // 48B rows: 16B-aligned, conflict-free
  constexpr int BROWS = TRANSB ? BN : BK;
  constexpr int BP = TRANSB ? 24 : (BN + 8);        // 48B / 144B rows

  __shared__ __align__(16) __nv_bfloat16 Ah[2][BM][AP];
  __shared__ __align__(16) __nv_bfloat16 Al[2][BM][AP];
  __shared__ __align__(16) __nv_bfloat16 Bh[2][BROWS][BP];
  __shared__ __align__(16) __nv_bfloat16 Bl[2][BROWS][BP];

  const int m0 = blockIdx.y * BM;
  const int n0 = blockIdx.x * BN;
  if (maskMode == 1 && n0 >= m0 + BM) return;   // fully masked score tile

  const int tid  = threadIdx.x;
  const int wid  = tid >> 5;
  const int lane = tid & 31;
  const int grp  = lane >> 2;
  const int tig  = lane & 3;

  const int z  = blockIdx.z;
  const int zo = z / batchInner;
  const int zi = z - zo * batchInner;
  const float* A  = Ag + zo*sA1 + zi*sA2;
  const float* Bp = Bg + zo*sB1 + zi*sB2;
  float*       C  = Cg + zo*sC1 + zi*sC2;

  const int wm = (wid / WARPS_N) * WM;
  const int wn = (wid % WARPS_N) * WN;

  float acc[MF][NF][4];
  #pragma unroll
  for (int i=0;i<MF;i++)
    #pragma unroll
    for (int j=0;j<NF;j++)
      #pragma unroll
      for (int r=0;r<4;r++) acc[i][j][r] = 0.f;

  int Keff = K;
  if (maskMode == 2) Keff = (m0 + BM < K) ? (m0 + BM) : K;  // AV: keys < m0+128
  const int nch = Keff / BK;

  // register staging for global tiles
  float4 aReg[2];
  constexpr int NB4 = TRANSB ? 1 : (BK*BN/4/256);   // float4 per thread (1)
  float4 bReg[NB4];

  const int aRow0 = tid >> 2;            // 0..63 (i=0), +64 (i=1)
  const int aKg   = tid & 3;
  const int btN   = tid >> 2;            // NT: 0..63 row
  const int btK   = (tid & 3) * 4;       // NT: k offset

  auto ldgA = [&](int c){
    int k0 = c * BK;
    #pragma unroll
    for (int i=0;i<2;i++){
      int row = aRow0 + i*64;
      aReg[i] = *reinterpret_cast<const float4*>(A + (size_t)(m0+row)*lda + k0 + aKg*4);
    }
  };
  auto stsA = [&](int buf){
    #pragma unroll
    for (int i=0;i<2;i++){
      int row = aRow0 + i*64;
      uint32_t h0,l0,h1,l1;
      split_bf16_pair(aReg[i].x, aReg[i].y, h0, l0);
      split_bf16_pair(aReg[i].z, aReg[i].w, h1, l1);
      *reinterpret_cast<uint2*>(&Ah[buf][row][aKg*4]) = make_uint2(h0,h1);
      *reinterpret_cast<uint2*>(&Al[buf][row][aKg*4]) = make_uint2(l0,l1);
    }
  };

  auto ldgB = [&](int c){
    int k0 = c * BK;
    if (TRANSB){
      bReg[0] = *reinterpret_cast<const float4*>(Bp + (size_t)(n0+btN)*ldb + k0 + btK);
    } else {
      #pragma unroll
      for (int i=0;i<NB4;i++){
        int idx = i*256 + tid;
        int k  = idx / (BN/4);
        int ng = idx % (BN/4);
        int gn = n0 + ng*4;
        if (gn < N)
          bReg[i] = *reinterpret_cast<const float4*>(Bp + (size_t)(k0+k)*ldb + gn);
        else
          bReg[i] = make_float4(0.f,0.f,0.f,0.f);
      }
    }
  };
  auto stsB = [&](int buf){
    if (TRANSB){
      uint32_t h0,l0,h1,l1;
      split_bf16_pair(bReg[0].x, bReg[0].y, h0, l0);
      split_bf16_pair(bReg[0].z, bReg[0].w, h1, l1);
      *reinterpret_cast<uint2*>(&Bh[buf][btN][btK]) = make_uint2(h0,h1);
      *reinterpret_cast<uint2*>(&Bl[buf][btN][btK]) = make_uint2(l0,l1);
    } else {
      #pragma unroll
      for (int i=0;i<NB4;i++){
        int idx = i*256 + tid;
        int k  = idx / (BN/4);
        int ng = idx % (BN/4);
        uint32_t h0,l0,h1,l1;
        split_bf16_pair(bReg[i].x, bReg[i].y, h0, l0);
        split_bf16_pair(bReg[i].z, bReg[i].w, h1, l1);
        *reinterpret_cast<uint2*>(&Bh[buf][k][ng*4]) = make_uint2(h0,h1);
        *reinterpret_cast<uint2*>(&Bl[buf][k][ng*4]) = make_uint2(l0,l1);
      }
    }
  };

  // ldmatrix lane decodes
  const int lrow = lane & 7;
  const int lsel = (lane >> 3) & 1;
  const int lhi  = lane >> 4;

  // ---- prologue ----
  ldgA(0); ldgB(0);
  stsA(0); stsB(0);
  __syncthreads();

  for (int c = 0; c < nch; c++){
    const int buf = c & 1;
    if (c+1 < nch){ ldgA(c+1); ldgB(c+1); }

    // ---- fragment loads via ldmatrix (from buf) ----
    uint32_t ah[MF][4], al[MF][4];
    #pragma unroll
    for (int mf=0; mf<MF; mf++){
      int r = wm + mf*16 + lsel*8 + lrow;
      ldsm_x4(ah[mf], smem_u32(&Ah[buf][r][lhi*8]));
      ldsm_x4(al[mf], smem_u32(&Al[buf][r][lhi*8]));
    }
    uint32_t bh[NF][2], bl[NF][2];
    #pragma unroll
    for (int nfp=0; nfp<NF/2; nfp++){
      int nb = wn + nfp*16;
      uint32_t rh[4], rl[4];
      if (TRANSB){
        int r = nb + lhi*8 + lrow;
        ldsm_x4(rh, smem_u32(&Bh[buf][r][lsel*8]));
        ldsm_x4(rl, smem_u32(&Bl[buf][r][lsel*8]));
      } else {
        int r = lsel*8 + lrow;
        ldsm_x4_t(rh, smem_u32(&Bh[buf][r][nb + lhi*8]));
        ldsm_x4_t(rl, smem_u32(&Bl[buf][r][nb + lhi*8]));
      }
      bh[2*nfp][0]=rh[0]; bh[2*nfp][1]=rh[1]; bh[2*nfp+1][0]=rh[2]; bh[2*nfp+1][1]=rh[3];
      bl[2*nfp][0]=rl[0]; bl[2*nfp][1]=rl[1]; bl[2*nfp+1][0]=rl[2]; bl[2*nfp+1][1]=rl[3];
    }

    // ---- MMA group 1: hi*hi (hides LDG latency before the STS) ----
    #pragma unroll
    for (int mf=0; mf<MF; mf++)
      #pragma unroll
      for (int nf=0; nf<NF; nf++)
        mma_bf16(acc[mf][nf], ah[mf], bh[nf]);

    // store NEXT tile into the other buffer (protected by previous bar)
    if (c+1 < nch){
      stsA(buf^1); stsB(buf^1);
    }

    // ---- MMA group 2: cross terms (overlap other warps' store/barrier) ----
    #pragma unroll
    for (int mf=0; mf<MF; mf++)
      #pragma unroll
      for (int nf=0; nf<NF; nf++){
        mma_bf16(acc[mf][nf], al[mf], bh[nf]);
        mma_bf16(acc[mf][nf], ah[mf], bl[nf]);
      }

    __syncthreads();
  }

  // ---- epilogue ----
  #pragma unroll
  for (int mf=0; mf<MF; mf++){
    #pragma unroll
    for (int nf=0; nf<NF; nf++){
      int row = m0 + wm + mf*16 + grp;
      int col = n0 + wn + nf*8 + tig*2;
      if (col < N){
        float2 v0 = make_float2(acc[mf][nf][0], acc[mf][nf][1]);
        float2 v1 = make_float2(acc[mf][nf][2], acc[mf][nf][3]);
        if (bias){
          float2 bv = *reinterpret_cast<const float2*>(bias + col);
          v0.x += bv.x; v0.y += bv.y;
          v1.x += bv.x; v1.y += bv.y;
        }
        if (ACT == 1){
          v0.x = gelu_exact(v0.x); v0.y = gelu_exact(v0.y);
          v1.x = gelu_exact(v1.x); v1.y = gelu_exact(v1.y);
        }
        *reinterpret_cast<float2*>(C + (size_t)row*ldc + col)     = v0;
        *reinterpret_cast<float2*>(C + (size_t)(row+8)*ldc + col) = v1;
      }
    }
  }
}

// ---------------- QKV weight/bias packing ------------------------------------
__global__ void pack_qkv_kernel(const float* __restrict__ Wq,
                                const float* __restrict__ Wk,
                                const float* __restrict__ Wv,
                                const float* __restrict__ bq,
                                const float* __restrict__ bk,
                                const float* __restrict__ bv)
{
  const size_t total = (size_t)LL*HH*QKVW;
  for (size_t idx = (size_t)blockIdx.x*blockDim.x + threadIdx.x;
       idx < total; idx += (size_t)gridDim.x*blockDim.x){
    int col = (int)(idx % QKVW);
    size_t rl = idx / QKVW;            // l*HH + row
    float v;
    if (col < HH)        v = Wq[rl*HH + col];
    else if (col < 2*HH) v = Wk[rl*HH + col - HH];
    else                 v = Wv[rl*HH + col - 2*HH];
    g_wqkv[idx] = v;
  }
  for (size_t idx = (size_t)blockIdx.x*blockDim.x + threadIdx.x;
       idx < (size_t)LL*QKVW; idx += (size_t)gridDim.x*blockDim.x){
    int col = (int)(idx % QKVW);
    int l   = (int)(idx / QKVW);
    float v;
    if (col < HH)        v = bq[l*HH + col];
    else if (col < 2*HH) v = bk[l*HH + col - HH];
    else                 v = bv[l*HH + col - 2*HH];
    g_bqkv[idx] = v;
  }
}

// ---------------- embeddings + LN --------------------------------------------
__global__ void embed_ln_kernel(const int* __restrict__ ids,
                                const float* __restrict__ we,
                                const float* __restrict__ pe,
                                const float* __restrict__ te,
                                const float* __restrict__ g,
                                const float* __restrict__ b)
{
  int t = blockIdx.x;
  int s = t & (SS-1);
  int id = ids[t];
  const float* wrow = we + (size_t)id*HH;
  const float* prow = pe + (size_t)s*HH;
  float x[3];
  float lsum = 0.f;
  #pragma unroll
  for (int i=0;i<3;i++){
    int c = threadIdx.x + i*256;
    x[i] = wrow[c] + prow[c] + te[c];
    lsum += x[i];
  }
  float mean = blockSum<8>(lsum) * (1.0f/HH);
  float ls2 = 0.f;
  #pragma unroll
  for (int i=0;i<3;i++){ x[i] -= mean; ls2 += x[i]*x[i]; }
  float var = blockSum<8>(ls2) * (1.0f/HH);
  float inv = rsqrtf(var + 1e-12f);
  #pragma unroll
  for (int i=0;i<3;i++){
    int c = threadIdx.x + i*256;
    g_h[(size_t)t*HH + c] = x[i]*inv*g[c] + b[c];
  }
}

// ---------------- residual + LN (in place on g_h) ----------------------------
__global__ void resln_kernel(const float* __restrict__ r,
                             const float* __restrict__ g,
                             const float* __restrict__ b)
{
  int t = blockIdx.x;
  float x[3];
  float lsum = 0.f;
  #pragma unroll
  for (int i=0;i<3;i++){
    int c = threadIdx.x + i*256;
    x[i] = g_h[(size_t)t*HH + c] + r[(size_t)t*HH + c];
    lsum += x[i];
  }
  float mean = blockSum<8>(lsum) * (1.0f/HH);
  float ls2 = 0.f;
  #pragma unroll
  for (int i=0;i<3;i++){ x[i] -= mean; ls2 += x[i]*x[i]; }
  float var = blockSum<8>(ls2) * (1.0f/HH);
  float inv = rsqrtf(var + 1e-12f);
  #pragma unroll
  for (int i=0;i<3;i++){
    int c = threadIdx.x + i*256;
    g_h[(size_t)t*HH + c] = x[i]*inv*g[c] + b[c];
  }
}

// ---------------- masked softmax over scores (in place, truncated) -----------
// Row s: valid keys j satisfy j<PLEN or j<=s -> contiguous [0, L), L=max(128,s+1).
// Zero-fill [L, E) where E = (s/128+1)*128 so the K-truncated AV GEMM reads
// exact zeros for intra-block masked entries. Region j >= E is never read.
__global__ void softmax_kernel()
{
  int z = blockIdx.y;
  int s = blockIdx.x;
  float* row = g_scores + ((size_t)z*SS + s)*SS;
  const int L = (s < PLEN) ? PLEN : (s + 1);
  const int E = (s/128 + 1) * 128;
  float x[4];
  float mx = -3.4e38f;
  #pragma unroll
  for (int i=0;i<4;i++){
    int j = threadIdx.x + i*128;
    x[i] = (j < L) ? row[j] * 0.125f : -3.4e38f;
    mx = fmaxf(mx, x[i]);
  }
  mx = blockMax<4>(mx);
  float ls = 0.f;
  #pragma unroll
  for (int i=0;i<4;i++){
    int j = threadIdx.x + i*128;
    x[i] = (j < L) ? __expf(x[i] - mx) : 0.f;
    ls += x[i];
  }
  float sum = blockSum<4>(ls);
  float inv = 1.0f / sum;
  #pragma unroll
  for (int i=0;i<4;i++){
    int j = threadIdx.x + i*128;
    if (j < L)      row[j] = x[i] * inv;
    else if (j < E) row[j] = 0.f;
  }
}

// ---------------- cross entropy over valid rows ------------------------------
__global__ void zero_loss_kernel(){ g_loss_sum = 0.f; }

__global__ void ce_kernel(const int* __restrict__ labels)
{
  int r = blockIdx.x;
  int bb = r / NVALID_PER_B;
  int s  = PLEN + (r - bb*NVALID_PER_B);
  const float* row = g_logits + (size_t)r*VV;
  int lab = labels[bb*SS + s];

  float mx = -3.4e38f;
  for (int j = threadIdx.x; j < VV; j += 256) mx = fmaxf(mx, row[j]);
  mx = blockMax<8>(mx);
  float ls = 0.f;
  for (int j = threadIdx.x; j < VV; j += 256) ls += __expf(row[j] - mx);
  float sum = blockSum<8>(ls);
  if (threadIdx.x == 0){
    float nll = (logf(sum) + mx) - row[lab];
    atomicAdd(&g_loss_sum, nll);
  }
}

__global__ void finalize_kernel(float* out){
  out[0] = g_loss_sum * (1.0f/(float)NVALID);
}

// ---------------- host orchestration -----------------------------------------
template<int BN, bool TRANSB, int ACT>
static void launch_mm(const float* A, const float* B, const float* bias, float* C,
                      int M, int N, int K, int lda, int ldb, int ldc,
                      int batchInner,
                      long long sA1, long long sA2, long long sB1, long long sB2,
                      long long sC1, long long sC2, int gz, int maskMode = 0)
{
  dim3 grid((N + BN - 1)/BN, M/128, gz);
  gemm_mma<BN,TRANSB,ACT><<<grid, 256>>>(
      A, B, bias, C, M, N, K, lda, ldb, ldc,
      batchInner, sA1, sA2, sB1, sB2, sC1, sC2, maskMode);
}

extern "C" void kernel_launch(void* const* d_in, const int* in_sizes, int n_in,
                              void* d_out, int out_size)
{
  const int*   input_ids = (const int*)  d_in[0];
  const int*   labels    = (const int*)  d_in[1];
  const float* word_emb  = (const float*)d_in[2];
  const float* pos_emb   = (const float*)d_in[3];
  const float* type_emb  = (const float*)d_in[4];
  const float* eg        = (const float*)d_in[5];
  const float* eb        = (const float*)d_in[6];
  const float* Wq = (const float*)d_in[7];  const float* bq = (const float*)d_in[8];
  const float* Wk = (const float*)d_in[9];  const float* bk = (const float*)d_in[10];
  const float* Wv = (const float*)d_in[11]; const float* bv = (const float*)d_in[12];
  const float* Wo = (const float*)d_in[13]; const float* bo = (const float*)d_in[14];
  const float* ln1g = (const float*)d_in[15]; const float* ln1b = (const float*)d_in[16];
  const float* W1 = (const float*)d_in[17]; const float* bf1 = (const float*)d_in[18];
  const float* W2 = (const float*)d_in[19]; const float* bf2 = (const float*)d_in[20];
  const float* ln2g = (const float*)d_in[21]; const float* ln2b = (const float*)d_in[22];
  const float* Wc = (const float*)d_in[23]; const float* bc = (const float*)d_in[24];
  float* out = (float*)d_out;

  float *p_h, *p_qkv, *p_ctx, *p_tmp, *p_ffn, *p_sc, *p_lg, *p_wqkv, *p_bqkv;
  cudaGetSymbolAddress((void**)&p_h,    g_h);
  cudaGetSymbolAddress((void**)&p_qkv,  g_qkv);
  cudaGetSymbolAddress((void**)&p_ctx,  g_ctx);
  cudaGetSymbolAddress((void**)&p_tmp,  g_tmp);
  cudaGetSymbolAddress((void**)&p_ffn,  g_ffn);
  cudaGetSymbolAddress((void**)&p_sc,   g_scores);
  cudaGetSymbolAddress((void**)&p_lg,   g_logits);
  cudaGetSymbolAddress((void**)&p_wqkv, g_wqkv);
  cudaGetSymbolAddress((void**)&p_bqkv, g_bqkv);

  zero_loss_kernel<<<1,1>>>();
  pack_qkv_kernel<<<1024,256>>>(Wq, Wk, Wv, bq, bk, bv);
  embed_ln_kernel<<<NTOK,256>>>(input_ids, word_emb, pos_emb, type_emb, eg, eb);

  const long long HDsq = (long long)HH*HH;
  const long long headStride = (long long)SS*HH;
  const long long qkvBatch   = (long long)SS*QKVW;
  const long long scStrideH  = (long long)SS*SS;
  const long long scStrideB  = (long long)NHH*SS*SS;

  for (int l = 0; l < LL; l++) {
    const float* wo = Wo + (size_t)l*HDsq; const float* bol = bo + (size_t)l*HH;
    const float* w1 = W1 + (size_t)l*HH*FFF; const float* b1l = bf1 + (size_t)l*FFF;
    const float* w2 = W2 + (size_t)l*FFF*HH; const float* b2l = bf2 + (size_t)l*HH;

    // fused QKV projection: [4096,768] @ [768,2304] + b (NN)
    launch_mm<64,false,0>(p_h, p_wqkv + (size_t)l*HH*QKVW, p_bqkv + (size_t)l*QKVW,
                          p_qkv, NTOK, QKVW, HH, HH, QKVW, QKVW,
                          1, 0,0, 0,0, 0,0, 1);

    // scores = q @ k^T (NT), prefix-LM dead tiles skipped (maskMode=1)
    launch_mm<64,true,0>(p_qkv, p_qkv + HH, nullptr, p_sc,
                         SS, SS, DHH, QKVW, QKVW, SS,
                         NHH,
                         qkvBatch, (long long)DHH,
                         qkvBatch, (long long)DHH,
                         scStrideB, scStrideH, BB*NHH, 1);

    softmax_kernel<<<dim3(SS, BB*NHH), 128>>>();

    // ctx = attn @ v (NN), K truncated at m0+128 (maskMode=2)
    launch_mm<64,false,0>(p_sc, p_qkv + 2*HH, nullptr, p_ctx,
                          SS, DHH, SS, SS, QKVW, HH,
                          NHH,
                          scStrideB, scStrideH,
                          qkvBatch, (long long)DHH,
                          headStride, (long long)DHH, BB*NHH, 2);

    // output proj + residual LN
    launch_mm<64,false,0>(p_ctx, wo, bol, p_tmp, NTOK, HH, HH, HH, HH, HH,
                          1, 0,0, 0,0, 0,0, 1);
    resln_kernel<<<NTOK,256>>>(p_tmp, ln1g + (size_t)l*HH, ln1b + (size_t)l*HH);

    // FFN
    launch_mm<64,false,1>(p_h, w1, b1l, p_ffn, NTOK, FFF, HH, HH, FFF, FFF,
                          1, 0,0, 0,0, 0,0, 1);   // fused GELU
    launch_mm<64,false,0>(p_ffn, w2, b2l, p_tmp, NTOK, HH, FFF, FFF, HH, HH,
                          1, 0,0, 0,0, 0,0, 1);
    resln_kernel<<<NTOK,256>>>(p_tmp, ln2g + (size_t)l*HH, ln2b + (size_t)l*HH);
  }

  // logits for valid tokens only (rows s in [128,512) per batch, contiguous)
  launch_mm<64,false,0>(p_h + (size_t)PLEN*HH, Wc, bc, p_lg,
                        NVALID_PER_B, VV, HH, HH, VV, VV,
                        1,
                        (long long)SS*HH, 0,
                        0, 0,
                        (long long)NVALID_PER_B*VV, 0, BB);

  ce_kernel<<<NVALID,256>>>(labels);
  finalize_kernel<<<1,1>>>(out);
}